// round 9
// baseline (speedup 1.0000x reference)
#include <cuda_runtime.h>
#include <cuda_bf16.h>
#include <cstdint>

#define VOCAB 500000
#define DIM 128
#define RANK 8
#define SCALING 2.0f
#define RANK_THRESHOLD 0.1f

#define NWARPS 8
#define STAGES 8
#define CHUNK 64

#define NBUCK 1024
#define BUCK_SHIFT 9          // bucket = idx >> 9  (500000 >> 9 = 976 buckets used)
#define MAXTOK (1 << 20)

// ---- sort scratch (static device arrays; no allocation) ----
__device__ int g_hist[NBUCK];
__device__ int g_offs[NBUCK];
__device__ int g_pos[MAXTOK];   // original token position, index-sorted order
__device__ int g_idx[MAXTOK];   // vocab index, same order

__device__ __forceinline__ void cp_async16(uint32_t smem_addr, const void* gptr) {
    asm volatile("cp.async.cg.shared.global [%0], [%1], 16;\n"
                 :: "r"(smem_addr), "l"(gptr));
}
__device__ __forceinline__ void cp_commit() {
    asm volatile("cp.async.commit_group;\n");
}

// ---- packed f32x2 helpers ----
__device__ __forceinline__ uint64_t pack2(float lo, float hi) {
    uint64_t r; asm("mov.b64 %0, {%1, %2};" : "=l"(r) : "f"(lo), "f"(hi)); return r;
}
__device__ __forceinline__ uint64_t bcast2(float v) {
    uint64_t r; asm("mov.b64 %0, {%1, %1};" : "=l"(r) : "f"(v)); return r;
}
__device__ __forceinline__ uint64_t fma2(uint64_t a, uint64_t b, uint64_t c) {
    uint64_t d; asm("fma.rn.f32x2 %0, %1, %2, %3;" : "=l"(d) : "l"(a), "l"(b), "l"(c)); return d;
}
__device__ __forceinline__ void unpack2(uint64_t v, float& lo, float& hi) {
    asm("mov.b64 {%0, %1}, %2;" : "=f"(lo), "=f"(hi) : "l"(v));
}

// warp-uniform index-dtype detection (first 32 int64 views)
__device__ __forceinline__ bool detect_is64(const void* xv) {
    const long long* x64 = reinterpret_cast<const long long*>(xv);
    long long probe = x64[threadIdx.x & 31];
    bool bad = (probe < 0) || (probe >= (long long)VOCAB);
    return (__ballot_sync(0xFFFFFFFFu, bad) == 0u);
}

// ---------------- sort kernels ----------------
__global__ void zero_hist_kernel() {
    g_hist[threadIdx.x] = 0;
}

__global__ void __launch_bounds__(256)
hist_kernel(const void* __restrict__ xv, int ntok) {
    __shared__ int sh[NBUCK];
    for (int i = threadIdx.x; i < NBUCK; i += blockDim.x) sh[i] = 0;
    __syncthreads();
    const bool is64 = detect_is64(xv);
    const long long* x64 = reinterpret_cast<const long long*>(xv);
    const int*       x32 = reinterpret_cast<const int*>(xv);
    for (int t = blockIdx.x * blockDim.x + threadIdx.x; t < ntok;
         t += gridDim.x * blockDim.x) {
        uint32_t idx = is64 ? (uint32_t)x64[t] : (uint32_t)x32[t];
        atomicAdd(&sh[idx >> BUCK_SHIFT], 1);
    }
    __syncthreads();
    for (int i = threadIdx.x; i < NBUCK; i += blockDim.x)
        if (sh[i]) atomicAdd(&g_hist[i], sh[i]);
}

__global__ void __launch_bounds__(NBUCK)
scan_kernel() {
    __shared__ int sh[NBUCK];
    int v = g_hist[threadIdx.x];
    sh[threadIdx.x] = v;
    __syncthreads();
    // Hillis-Steele inclusive scan -> convert to exclusive
    for (int off = 1; off < NBUCK; off <<= 1) {
        int add = (threadIdx.x >= off) ? sh[threadIdx.x - off] : 0;
        __syncthreads();
        sh[threadIdx.x] += add;
        __syncthreads();
    }
    g_offs[threadIdx.x] = sh[threadIdx.x] - v;   // exclusive
}

__global__ void __launch_bounds__(256)
scatter_kernel(const void* __restrict__ xv, int ntok) {
    const bool is64 = detect_is64(xv);
    const long long* x64 = reinterpret_cast<const long long*>(xv);
    const int*       x32 = reinterpret_cast<const int*>(xv);
    for (int t = blockIdx.x * blockDim.x + threadIdx.x; t < ntok;
         t += gridDim.x * blockDim.x) {
        uint32_t idx = is64 ? (uint32_t)x64[t] : (uint32_t)x32[t];
        int p = atomicAdd(&g_offs[idx >> BUCK_SHIFT], 1);
        g_pos[p] = t;
        g_idx[p] = (int)idx;
    }
}

// ---------------- main gather kernel (index-sorted order) ----------------
__global__ void __launch_bounds__(NWARPS * 32)
cora_embed_kernel(const float* __restrict__ E,     // [VOCAB, 128]
                  const float* __restrict__ A,     // [8, 128]
                  const float* __restrict__ Bm,    // [VOCAB, 8]
                  const float* __restrict__ rp,    // [8]
                  float* __restrict__ out,         // [ntok, 128]
                  int ntok)
{
    __shared__ float e_buf[NWARPS][STAGES][DIM];   // 32 KB
    __shared__ float b_buf[NWARPS][STAGES][RANK];  // 2 KB

    const int lane = threadIdx.x & 31;
    const int w    = threadIdx.x >> 5;
    const int warp_global = blockIdx.x * NWARPS + w;

    uint64_t a2[RANK][2];
#pragma unroll
    for (int r = 0; r < RANK; r++) {
        float g = (rp[r] > RANK_THRESHOLD) ? SCALING : 0.0f;
        float4 av = reinterpret_cast<const float4*>(A)[r * (DIM / 4) + lane];
        a2[r][0] = pack2(av.x * g, av.y * g);
        a2[r][1] = pack2(av.z * g, av.w * g);
    }

    const int base = warp_global * CHUNK;
    if (base >= ntok) return;
    const int tend = min(base + CHUNK, ntok);
    const int nt = tend - base;

    const uint32_t e_base = (uint32_t)__cvta_generic_to_shared(&e_buf[w][0][0]);
    const uint32_t b_base = (uint32_t)__cvta_generic_to_shared(&b_buf[w][0][0]);

    // prologue
#pragma unroll
    for (int s = 0; s < STAGES; s++) {
        int t = base + s;
        if (t < tend) {
            uint32_t idx = (uint32_t)g_idx[t];
            cp_async16(e_base + (uint32_t)(s * DIM + lane * 4) * 4,
                       E + (size_t)idx * DIM + lane * 4);
            if (lane < 2)
                cp_async16(b_base + (uint32_t)(s * RANK + lane * 4) * 4,
                           Bm + (size_t)idx * RANK + lane * 4);
        }
        cp_commit();
    }

    // steady state
    for (int i = 0; i < nt; i++) {
        asm volatile("cp.async.wait_group %0;\n" :: "n"(STAGES - 1));
        __syncwarp();

        const int s = i & (STAGES - 1);
        float4 e  = *reinterpret_cast<const float4*>(&e_buf[w][s][lane * 4]);
        float4 b0 = *reinterpret_cast<const float4*>(&b_buf[w][s][0]);
        float4 b1 = *reinterpret_cast<const float4*>(&b_buf[w][s][4]);

        __syncwarp();

        int t = base + i + STAGES;
        if (t < tend) {
            uint32_t idx = (uint32_t)g_idx[t];
            cp_async16(e_base + (uint32_t)(s * DIM + lane * 4) * 4,
                       E + (size_t)idx * DIM + lane * 4);
            if (lane < 2)
                cp_async16(b_base + (uint32_t)(s * RANK + lane * 4) * 4,
                           Bm + (size_t)idx * RANK + lane * 4);
        }
        cp_commit();

        uint64_t o0 = pack2(e.x, e.y);
        uint64_t o1 = pack2(e.z, e.w);
        uint64_t bb;
        bb = bcast2(b0.x); o0 = fma2(bb, a2[0][0], o0); o1 = fma2(bb, a2[0][1], o1);
        bb = bcast2(b0.y); o0 = fma2(bb, a2[1][0], o0); o1 = fma2(bb, a2[1][1], o1);
        bb = bcast2(b0.z); o0 = fma2(bb, a2[2][0], o0); o1 = fma2(bb, a2[2][1], o1);
        bb = bcast2(b0.w); o0 = fma2(bb, a2[3][0], o0); o1 = fma2(bb, a2[3][1], o1);
        bb = bcast2(b1.x); o0 = fma2(bb, a2[4][0], o0); o1 = fma2(bb, a2[4][1], o1);
        bb = bcast2(b1.y); o0 = fma2(bb, a2[5][0], o0); o1 = fma2(bb, a2[5][1], o1);
        bb = bcast2(b1.z); o0 = fma2(bb, a2[6][0], o0); o1 = fma2(bb, a2[6][1], o1);
        bb = bcast2(b1.w); o0 = fma2(bb, a2[7][0], o0); o1 = fma2(bb, a2[7][1], o1);

        float4 o;
        unpack2(o0, o.x, o.y);
        unpack2(o1, o.z, o.w);

        int pos = g_pos[base + i];
        __stcs(reinterpret_cast<float4*>(out + (size_t)pos * DIM) + lane, o);
    }
}

// ---------------- fallback (direct order) for ntok > MAXTOK ----------------
__global__ void __launch_bounds__(NWARPS * 32)
cora_embed_direct(const void* __restrict__ xv,
                  const float* __restrict__ E, const float* __restrict__ A,
                  const float* __restrict__ Bm, const float* __restrict__ rp,
                  float* __restrict__ out, int ntok)
{
    __shared__ float e_buf[NWARPS][STAGES][DIM];
    __shared__ float b_buf[NWARPS][STAGES][RANK];
    const int lane = threadIdx.x & 31;
    const int w    = threadIdx.x >> 5;
    const int warp_global = blockIdx.x * NWARPS + w;
    const bool is64 = detect_is64(xv);
    const long long* x64 = reinterpret_cast<const long long*>(xv);
    const int*       x32 = reinterpret_cast<const int*>(xv);

    uint64_t a2[RANK][2];
#pragma unroll
    for (int r = 0; r < RANK; r++) {
        float g = (rp[r] > RANK_THRESHOLD) ? SCALING : 0.0f;
        float4 av = reinterpret_cast<const float4*>(A)[r * (DIM / 4) + lane];
        a2[r][0] = pack2(av.x * g, av.y * g);
        a2[r][1] = pack2(av.z * g, av.w * g);
    }
    const int base = warp_global * CHUNK;
    if (base >= ntok) return;
    const int tend = min(base + CHUNK, ntok);
    const int nt = tend - base;
    const uint32_t e_base = (uint32_t)__cvta_generic_to_shared(&e_buf[w][0][0]);
    const uint32_t b_base = (uint32_t)__cvta_generic_to_shared(&b_buf[w][0][0]);
#pragma unroll
    for (int s = 0; s < STAGES; s++) {
        int t = base + s;
        if (t < tend) {
            uint32_t idx = is64 ? (uint32_t)x64[t] : (uint32_t)x32[t];
            cp_async16(e_base + (uint32_t)(s * DIM + lane * 4) * 4,
                       E + (size_t)idx * DIM + lane * 4);
            if (lane < 2)
                cp_async16(b_base + (uint32_t)(s * RANK + lane * 4) * 4,
                           Bm + (size_t)idx * RANK + lane * 4);
        }
        cp_commit();
    }
    for (int i = 0; i < nt; i++) {
        asm volatile("cp.async.wait_group %0;\n" :: "n"(STAGES - 1));
        __syncwarp();
        const int s = i & (STAGES - 1);
        float4 e  = *reinterpret_cast<const float4*>(&e_buf[w][s][lane * 4]);
        float4 b0 = *reinterpret_cast<const float4*>(&b_buf[w][s][0]);
        float4 b1 = *reinterpret_cast<const float4*>(&b_buf[w][s][4]);
        __syncwarp();
        int t = base + i + STAGES;
        if (t < tend) {
            uint32_t idx = is64 ? (uint32_t)x64[t] : (uint32_t)x32[t];
            cp_async16(e_base + (uint32_t)(s * DIM + lane * 4) * 4,
                       E + (size_t)idx * DIM + lane * 4);
            if (lane < 2)
                cp_async16(b_base + (uint32_t)(s * RANK + lane * 4) * 4,
                           Bm + (size_t)idx * RANK + lane * 4);
        }
        cp_commit();
        uint64_t o0 = pack2(e.x, e.y);
        uint64_t o1 = pack2(e.z, e.w);
        uint64_t bb;
        bb = bcast2(b0.x); o0 = fma2(bb, a2[0][0], o0); o1 = fma2(bb, a2[0][1], o1);
        bb = bcast2(b0.y); o0 = fma2(bb, a2[1][0], o0); o1 = fma2(bb, a2[1][1], o1);
        bb = bcast2(b0.z); o0 = fma2(bb, a2[2][0], o0); o1 = fma2(bb, a2[2][1], o1);
        bb = bcast2(b0.w); o0 = fma2(bb, a2[3][0], o0); o1 = fma2(bb, a2[3][1], o1);
        bb = bcast2(b1.x); o0 = fma2(bb, a2[4][0], o0); o1 = fma2(bb, a2[4][1], o1);
        bb = bcast2(b1.y); o0 = fma2(bb, a2[5][0], o0); o1 = fma2(bb, a2[5][1], o1);
        bb = bcast2(b1.z); o0 = fma2(bb, a2[6][0], o0); o1 = fma2(bb, a2[6][1], o1);
        bb = bcast2(b1.w); o0 = fma2(bb, a2[7][0], o0); o1 = fma2(bb, a2[7][1], o1);
        float4 o;
        unpack2(o0, o.x, o.y);
        unpack2(o1, o.z, o.w);
        __stcs(reinterpret_cast<float4*>(out + (size_t)(base + i) * DIM) + lane, o);
    }
}

extern "C" void kernel_launch(void* const* d_in, const int* in_sizes, int n_in,
                              void* d_out, int out_size)
{
    const void*  x  = d_in[0];
    const float* E  = (const float*)d_in[1];
    const float* A  = (const float*)d_in[2];
    const float* Bm = (const float*)d_in[3];
    const float* rp = (const float*)d_in[4];
    float* out = (float*)d_out;

    const int ntok = out_size / DIM;
    const int tok_per_block = NWARPS * CHUNK;                 // 512
    int blocks = (ntok + tok_per_block - 1) / tok_per_block;  // 1600

    if (ntok <= MAXTOK && ntok >= 32) {
        zero_hist_kernel<<<1, NBUCK>>>();
        hist_kernel<<<256, 256>>>(x, ntok);
        scan_kernel<<<1, NBUCK>>>();
        scatter_kernel<<<256, 256>>>(x, ntok);
        cora_embed_kernel<<<blocks, NWARPS * 32>>>(E, A, Bm, rp, out, ntok);
    } else {
        cora_embed_direct<<<blocks, NWARPS * 32>>>(x, E, A, Bm, rp, out, ntok);
    }
}

// round 10
// speedup vs baseline: 1.3590x; 1.3590x over previous
#include <cuda_runtime.h>
#include <cuda_bf16.h>
#include <cstdint>

#define VOCAB 500000
#define DIM 128
#define RANK 8
#define SCALING 2.0f
#define RANK_THRESHOLD 0.1f

#define NWARPS 8
#define STAGES 8
#define CHUNK 64

#define NBUCK 1024
#define BUCK_SHIFT 9          // bucket = idx >> 9
#define MAXTOK (1 << 20)
#define SCHUNK 8192           // tokens per scatter block

// ---- sort scratch (static device arrays; no allocation) ----
__device__ int  g_hist[NBUCK];
__device__ int  g_offs[NBUCK];
__device__ int2 g_sorted[MAXTOK];   // .x = original pos, .y = vocab idx

__device__ __forceinline__ void cp_async16(uint32_t smem_addr, const void* gptr) {
    asm volatile("cp.async.cg.shared.global [%0], [%1], 16;\n"
                 :: "r"(smem_addr), "l"(gptr));
}
__device__ __forceinline__ void cp_commit() {
    asm volatile("cp.async.commit_group;\n");
}

// ---- packed f32x2 helpers ----
__device__ __forceinline__ uint64_t pack2(float lo, float hi) {
    uint64_t r; asm("mov.b64 %0, {%1, %2};" : "=l"(r) : "f"(lo), "f"(hi)); return r;
}
__device__ __forceinline__ uint64_t bcast2(float v) {
    uint64_t r; asm("mov.b64 %0, {%1, %1};" : "=l"(r) : "f"(v)); return r;
}
__device__ __forceinline__ uint64_t fma2(uint64_t a, uint64_t b, uint64_t c) {
    uint64_t d; asm("fma.rn.f32x2 %0, %1, %2, %3;" : "=l"(d) : "l"(a), "l"(b), "l"(c)); return d;
}
__device__ __forceinline__ void unpack2(uint64_t v, float& lo, float& hi) {
    asm("mov.b64 {%0, %1}, %2;" : "=f"(lo), "=f"(hi) : "l"(v));
}

// warp-uniform index-dtype detection (first 32 int64 views)
__device__ __forceinline__ bool detect_is64(const void* xv) {
    const long long* x64 = reinterpret_cast<const long long*>(xv);
    long long probe = x64[threadIdx.x & 31];
    bool bad = (probe < 0) || (probe >= (long long)VOCAB);
    return (__ballot_sync(0xFFFFFFFFu, bad) == 0u);
}

// ---------------- sort kernels ----------------
__global__ void zero_hist_kernel() {
    g_hist[threadIdx.x] = 0;
}

__global__ void __launch_bounds__(256)
hist_kernel(const void* __restrict__ xv, int ntok) {
    __shared__ int sh[NBUCK];
    for (int i = threadIdx.x; i < NBUCK; i += blockDim.x) sh[i] = 0;
    __syncthreads();
    const bool is64 = detect_is64(xv);
    const long long* x64 = reinterpret_cast<const long long*>(xv);
    const int*       x32 = reinterpret_cast<const int*>(xv);
    for (int t = blockIdx.x * blockDim.x + threadIdx.x; t < ntok;
         t += gridDim.x * blockDim.x) {
        uint32_t idx = is64 ? (uint32_t)x64[t] : (uint32_t)x32[t];
        atomicAdd(&sh[idx >> BUCK_SHIFT], 1);
    }
    __syncthreads();
    for (int i = threadIdx.x; i < NBUCK; i += blockDim.x)
        if (sh[i]) atomicAdd(&g_hist[i], sh[i]);
}

__global__ void __launch_bounds__(NBUCK)
scan_kernel() {
    __shared__ int sh[NBUCK];
    int v = g_hist[threadIdx.x];
    sh[threadIdx.x] = v;
    __syncthreads();
    for (int off = 1; off < NBUCK; off <<= 1) {
        int add = (threadIdx.x >= off) ? sh[threadIdx.x - off] : 0;
        __syncthreads();
        sh[threadIdx.x] += add;
        __syncthreads();
    }
    g_offs[threadIdx.x] = sh[threadIdx.x] - v;   // exclusive scan
}

// Block-aggregated scatter: smem histogram -> one global reservation per
// non-empty bucket per block -> smem-cursor ranking -> coalesced int2 writes.
__global__ void __launch_bounds__(512)
scatter_kernel(const void* __restrict__ xv, int ntok) {
    __shared__ int s_cnt[NBUCK];
    __shared__ int s_base[NBUCK];

    const bool is64 = detect_is64(xv);
    const long long* x64 = reinterpret_cast<const long long*>(xv);
    const int*       x32 = reinterpret_cast<const int*>(xv);

    const int start = blockIdx.x * SCHUNK;
    const int end   = min(start + SCHUNK, ntok);

    for (int i = threadIdx.x; i < NBUCK; i += blockDim.x) s_cnt[i] = 0;
    __syncthreads();

    // pass 1: local histogram (smem atomics, ~8/bucket avg)
    for (int t = start + threadIdx.x; t < end; t += blockDim.x) {
        uint32_t idx = is64 ? (uint32_t)x64[t] : (uint32_t)x32[t];
        atomicAdd(&s_cnt[idx >> BUCK_SHIFT], 1);
    }
    __syncthreads();

    // reserve global ranges (one global atomic per non-empty bucket per block)
    for (int b = threadIdx.x; b < NBUCK; b += blockDim.x)
        s_base[b] = s_cnt[b] ? atomicAdd(&g_offs[b], s_cnt[b]) : 0;
    __syncthreads();

    // pass 2: rank via smem cursors, write (pos, idx) pairs
    for (int t = start + threadIdx.x; t < end; t += blockDim.x) {
        uint32_t idx = is64 ? (uint32_t)x64[t] : (uint32_t)x32[t];
        int p = atomicAdd(&s_base[idx >> BUCK_SHIFT], 1);
        g_sorted[p] = make_int2(t, (int)idx);
    }
}

// ---------------- main gather kernel (index-sorted order) ----------------
__global__ void __launch_bounds__(NWARPS * 32)
cora_embed_kernel(const float* __restrict__ E,     // [VOCAB, 128]
                  const float* __restrict__ A,     // [8, 128]
                  const float* __restrict__ Bm,    // [VOCAB, 8]
                  const float* __restrict__ rp,    // [8]
                  float* __restrict__ out,         // [ntok, 128]
                  int ntok)
{
    __shared__ float e_buf[NWARPS][STAGES][DIM];
    __shared__ float b_buf[NWARPS][STAGES][RANK];

    const int lane = threadIdx.x & 31;
    const int w    = threadIdx.x >> 5;
    const int warp_global = blockIdx.x * NWARPS + w;

    uint64_t a2[RANK][2];
#pragma unroll
    for (int r = 0; r < RANK; r++) {
        float g = (rp[r] > RANK_THRESHOLD) ? SCALING : 0.0f;
        float4 av = reinterpret_cast<const float4*>(A)[r * (DIM / 4) + lane];
        a2[r][0] = pack2(av.x * g, av.y * g);
        a2[r][1] = pack2(av.z * g, av.w * g);
    }

    const int base = warp_global * CHUNK;
    if (base >= ntok) return;
    const int tend = min(base + CHUNK, ntok);
    const int nt = tend - base;

    const uint32_t e_base = (uint32_t)__cvta_generic_to_shared(&e_buf[w][0][0]);
    const uint32_t b_base = (uint32_t)__cvta_generic_to_shared(&b_buf[w][0][0]);

#pragma unroll
    for (int s = 0; s < STAGES; s++) {
        int t = base + s;
        if (t < tend) {
            uint32_t idx = (uint32_t)g_sorted[t].y;
            cp_async16(e_base + (uint32_t)(s * DIM + lane * 4) * 4,
                       E + (size_t)idx * DIM + lane * 4);
            if (lane < 2)
                cp_async16(b_base + (uint32_t)(s * RANK + lane * 4) * 4,
                           Bm + (size_t)idx * RANK + lane * 4);
        }
        cp_commit();
    }

    for (int i = 0; i < nt; i++) {
        asm volatile("cp.async.wait_group %0;\n" :: "n"(STAGES - 1));
        __syncwarp();

        const int s = i & (STAGES - 1);
        float4 e  = *reinterpret_cast<const float4*>(&e_buf[w][s][lane * 4]);
        float4 b0 = *reinterpret_cast<const float4*>(&b_buf[w][s][0]);
        float4 b1 = *reinterpret_cast<const float4*>(&b_buf[w][s][4]);

        __syncwarp();

        int t = base + i + STAGES;
        if (t < tend) {
            uint32_t idx = (uint32_t)g_sorted[t].y;
            cp_async16(e_base + (uint32_t)(s * DIM + lane * 4) * 4,
                       E + (size_t)idx * DIM + lane * 4);
            if (lane < 2)
                cp_async16(b_base + (uint32_t)(s * RANK + lane * 4) * 4,
                           Bm + (size_t)idx * RANK + lane * 4);
        }
        cp_commit();

        uint64_t o0 = pack2(e.x, e.y);
        uint64_t o1 = pack2(e.z, e.w);
        uint64_t bb;
        bb = bcast2(b0.x); o0 = fma2(bb, a2[0][0], o0); o1 = fma2(bb, a2[0][1], o1);
        bb = bcast2(b0.y); o0 = fma2(bb, a2[1][0], o0); o1 = fma2(bb, a2[1][1], o1);
        bb = bcast2(b0.z); o0 = fma2(bb, a2[2][0], o0); o1 = fma2(bb, a2[2][1], o1);
        bb = bcast2(b0.w); o0 = fma2(bb, a2[3][0], o0); o1 = fma2(bb, a2[3][1], o1);
        bb = bcast2(b1.x); o0 = fma2(bb, a2[4][0], o0); o1 = fma2(bb, a2[4][1], o1);
        bb = bcast2(b1.y); o0 = fma2(bb, a2[5][0], o0); o1 = fma2(bb, a2[5][1], o1);
        bb = bcast2(b1.z); o0 = fma2(bb, a2[6][0], o0); o1 = fma2(bb, a2[6][1], o1);
        bb = bcast2(b1.w); o0 = fma2(bb, a2[7][0], o0); o1 = fma2(bb, a2[7][1], o1);

        float4 o;
        unpack2(o0, o.x, o.y);
        unpack2(o1, o.z, o.w);

        int pos = g_sorted[base + i].x;
        __stcs(reinterpret_cast<float4*>(out + (size_t)pos * DIM) + lane, o);
    }
}

// ---------------- fallback (direct order) ----------------
__global__ void __launch_bounds__(NWARPS * 32)
cora_embed_direct(const void* __restrict__ xv,
                  const float* __restrict__ E, const float* __restrict__ A,
                  const float* __restrict__ Bm, const float* __restrict__ rp,
                  float* __restrict__ out, int ntok)
{
    __shared__ float e_buf[NWARPS][STAGES][DIM];
    __shared__ float b_buf[NWARPS][STAGES][RANK];
    const int lane = threadIdx.x & 31;
    const int w    = threadIdx.x >> 5;
    const int warp_global = blockIdx.x * NWARPS + w;
    const bool is64 = detect_is64(xv);
    const long long* x64 = reinterpret_cast<const long long*>(xv);
    const int*       x32 = reinterpret_cast<const int*>(xv);

    uint64_t a2[RANK][2];
#pragma unroll
    for (int r = 0; r < RANK; r++) {
        float g = (rp[r] > RANK_THRESHOLD) ? SCALING : 0.0f;
        float4 av = reinterpret_cast<const float4*>(A)[r * (DIM / 4) + lane];
        a2[r][0] = pack2(av.x * g, av.y * g);
        a2[r][1] = pack2(av.z * g, av.w * g);
    }
    const int base = warp_global * CHUNK;
    if (base >= ntok) return;
    const int tend = min(base + CHUNK, ntok);
    const int nt = tend - base;
    const uint32_t e_base = (uint32_t)__cvta_generic_to_shared(&e_buf[w][0][0]);
    const uint32_t b_base = (uint32_t)__cvta_generic_to_shared(&b_buf[w][0][0]);
#pragma unroll
    for (int s = 0; s < STAGES; s++) {
        int t = base + s;
        if (t < tend) {
            uint32_t idx = is64 ? (uint32_t)x64[t] : (uint32_t)x32[t];
            cp_async16(e_base + (uint32_t)(s * DIM + lane * 4) * 4,
                       E + (size_t)idx * DIM + lane * 4);
            if (lane < 2)
                cp_async16(b_base + (uint32_t)(s * RANK + lane * 4) * 4,
                           Bm + (size_t)idx * RANK + lane * 4);
        }
        cp_commit();
    }
    for (int i = 0; i < nt; i++) {
        asm volatile("cp.async.wait_group %0;\n" :: "n"(STAGES - 1));
        __syncwarp();
        const int s = i & (STAGES - 1);
        float4 e  = *reinterpret_cast<const float4*>(&e_buf[w][s][lane * 4]);
        float4 b0 = *reinterpret_cast<const float4*>(&b_buf[w][s][0]);
        float4 b1 = *reinterpret_cast<const float4*>(&b_buf[w][s][4]);
        __syncwarp();
        int t = base + i + STAGES;
        if (t < tend) {
            uint32_t idx = is64 ? (uint32_t)x64[t] : (uint32_t)x32[t];
            cp_async16(e_base + (uint32_t)(s * DIM + lane * 4) * 4,
                       E + (size_t)idx * DIM + lane * 4);
            if (lane < 2)
                cp_async16(b_base + (uint32_t)(s * RANK + lane * 4) * 4,
                           Bm + (size_t)idx * RANK + lane * 4);
        }
        cp_commit();
        uint64_t o0 = pack2(e.x, e.y);
        uint64_t o1 = pack2(e.z, e.w);
        uint64_t bb;
        bb = bcast2(b0.x); o0 = fma2(bb, a2[0][0], o0); o1 = fma2(bb, a2[0][1], o1);
        bb = bcast2(b0.y); o0 = fma2(bb, a2[1][0], o0); o1 = fma2(bb, a2[1][1], o1);
        bb = bcast2(b0.z); o0 = fma2(bb, a2[2][0], o0); o1 = fma2(bb, a2[2][1], o1);
        bb = bcast2(b0.w); o0 = fma2(bb, a2[3][0], o0); o1 = fma2(bb, a2[3][1], o1);
        bb = bcast2(b1.x); o0 = fma2(bb, a2[4][0], o0); o1 = fma2(bb, a2[4][1], o1);
        bb = bcast2(b1.y); o0 = fma2(bb, a2[5][0], o0); o1 = fma2(bb, a2[5][1], o1);
        bb = bcast2(b1.z); o0 = fma2(bb, a2[6][0], o0); o1 = fma2(bb, a2[6][1], o1);
        bb = bcast2(b1.w); o0 = fma2(bb, a2[7][0], o0); o1 = fma2(bb, a2[7][1], o1);
        float4 o;
        unpack2(o0, o.x, o.y);
        unpack2(o1, o.z, o.w);
        __stcs(reinterpret_cast<float4*>(out + (size_t)(base + i) * DIM) + lane, o);
    }
}

extern "C" void kernel_launch(void* const* d_in, const int* in_sizes, int n_in,
                              void* d_out, int out_size)
{
    const void*  x  = d_in[0];
    const float* E  = (const float*)d_in[1];
    const float* A  = (const float*)d_in[2];
    const float* Bm = (const float*)d_in[3];
    const float* rp = (const float*)d_in[4];
    float* out = (float*)d_out;

    const int ntok = out_size / DIM;
    const int tok_per_block = NWARPS * CHUNK;
    int blocks = (ntok + tok_per_block - 1) / tok_per_block;

    if (ntok <= MAXTOK && ntok >= 32) {
        zero_hist_kernel<<<1, NBUCK>>>();
        hist_kernel<<<296, 256>>>(x, ntok);
        scan_kernel<<<1, NBUCK>>>();
        int sblocks = (ntok + SCHUNK - 1) / SCHUNK;
        scatter_kernel<<<sblocks, 512>>>(x, ntok);
        cora_embed_kernel<<<blocks, NWARPS * 32>>>(E, A, Bm, rp, out, ntok);
    } else {
        cora_embed_direct<<<blocks, NWARPS * 32>>>(x, E, A, Bm, rp, out, ntok);
    }
}

// round 11
// speedup vs baseline: 1.3596x; 1.0004x over previous
#include <cuda_runtime.h>
#include <cuda_bf16.h>
#include <cstdint>

#define VOCAB 500000
#define DIM 128
#define RANK 8
#define SCALING 2.0f
#define RANK_THRESHOLD 0.1f

#define NWARPS 8
#define STAGES 8
#define CHUNK 64

#define NBUCK 1024
#define BUCK_SHIFT 9          // bucket = idx >> 9
#define MAXTOK (1 << 20)
#define SCHUNK 2048           // tokens per scatter block (400 blocks @ 819k tokens)

// ---- sort scratch (static device arrays; no allocation) ----
// g_hist is zero at kernel_launch entry on every execution: device globals are
// zero-initialized, and scan_kernel re-zeroes g_hist after consuming it.
__device__ int  g_hist[NBUCK];
__device__ int  g_offs[NBUCK];
__device__ int2 g_sorted[MAXTOK];   // .x = original pos, .y = vocab idx

__device__ __forceinline__ void cp_async16(uint32_t smem_addr, const void* gptr) {
    asm volatile("cp.async.cg.shared.global [%0], [%1], 16;\n"
                 :: "r"(smem_addr), "l"(gptr));
}
__device__ __forceinline__ void cp_commit() {
    asm volatile("cp.async.commit_group;\n");
}

// ---- packed f32x2 helpers ----
__device__ __forceinline__ uint64_t pack2(float lo, float hi) {
    uint64_t r; asm("mov.b64 %0, {%1, %2};" : "=l"(r) : "f"(lo), "f"(hi)); return r;
}
__device__ __forceinline__ uint64_t bcast2(float v) {
    uint64_t r; asm("mov.b64 %0, {%1, %1};" : "=l"(r) : "f"(v)); return r;
}
__device__ __forceinline__ uint64_t fma2(uint64_t a, uint64_t b, uint64_t c) {
    uint64_t d; asm("fma.rn.f32x2 %0, %1, %2, %3;" : "=l"(d) : "l"(a), "l"(b), "l"(c)); return d;
}
__device__ __forceinline__ void unpack2(uint64_t v, float& lo, float& hi) {
    asm("mov.b64 {%0, %1}, %2;" : "=f"(lo), "=f"(hi) : "l"(v));
}

// warp-uniform index-dtype detection (first 32 int64 views)
__device__ __forceinline__ bool detect_is64(const void* xv) {
    const long long* x64 = reinterpret_cast<const long long*>(xv);
    long long probe = x64[threadIdx.x & 31];
    bool bad = (probe < 0) || (probe >= (long long)VOCAB);
    return (__ballot_sync(0xFFFFFFFFu, bad) == 0u);
}

// ---------------- sort kernels ----------------
__global__ void __launch_bounds__(256)
hist_kernel(const void* __restrict__ xv, int ntok) {
    __shared__ int sh[NBUCK];
    for (int i = threadIdx.x; i < NBUCK; i += blockDim.x) sh[i] = 0;
    __syncthreads();
    const bool is64 = detect_is64(xv);
    const long long* x64 = reinterpret_cast<const long long*>(xv);
    const int*       x32 = reinterpret_cast<const int*>(xv);
    for (int t = blockIdx.x * blockDim.x + threadIdx.x; t < ntok;
         t += gridDim.x * blockDim.x) {
        uint32_t idx = is64 ? (uint32_t)x64[t] : (uint32_t)x32[t];
        atomicAdd(&sh[idx >> BUCK_SHIFT], 1);
    }
    __syncthreads();
    for (int i = threadIdx.x; i < NBUCK; i += blockDim.x)
        if (sh[i]) atomicAdd(&g_hist[i], sh[i]);
}

__global__ void __launch_bounds__(NBUCK)
scan_kernel() {
    __shared__ int sh[NBUCK];
    int v = g_hist[threadIdx.x];
    g_hist[threadIdx.x] = 0;          // restore invariant for next replay
    sh[threadIdx.x] = v;
    __syncthreads();
    for (int off = 1; off < NBUCK; off <<= 1) {
        int add = (threadIdx.x >= off) ? sh[threadIdx.x - off] : 0;
        __syncthreads();
        sh[threadIdx.x] += add;
        __syncthreads();
    }
    g_offs[threadIdx.x] = sh[threadIdx.x] - v;   // exclusive scan
}

// Block-aggregated scatter: smem histogram -> one global reservation per
// non-empty bucket per block -> smem-cursor ranking -> coalesced int2 writes.
__global__ void __launch_bounds__(512)
scatter_kernel(const void* __restrict__ xv, int ntok) {
    __shared__ int s_cnt[NBUCK];
    __shared__ int s_base[NBUCK];

    const bool is64 = detect_is64(xv);
    const long long* x64 = reinterpret_cast<const long long*>(xv);
    const int*       x32 = reinterpret_cast<const int*>(xv);

    const int start = blockIdx.x * SCHUNK;
    const int end   = min(start + SCHUNK, ntok);

    for (int i = threadIdx.x; i < NBUCK; i += blockDim.x) s_cnt[i] = 0;
    __syncthreads();

    for (int t = start + threadIdx.x; t < end; t += blockDim.x) {
        uint32_t idx = is64 ? (uint32_t)x64[t] : (uint32_t)x32[t];
        atomicAdd(&s_cnt[idx >> BUCK_SHIFT], 1);
    }
    __syncthreads();

    for (int b = threadIdx.x; b < NBUCK; b += blockDim.x)
        s_base[b] = s_cnt[b] ? atomicAdd(&g_offs[b], s_cnt[b]) : 0;
    __syncthreads();

    for (int t = start + threadIdx.x; t < end; t += blockDim.x) {
        uint32_t idx = is64 ? (uint32_t)x64[t] : (uint32_t)x32[t];
        int p = atomicAdd(&s_base[idx >> BUCK_SHIFT], 1);
        g_sorted[p] = make_int2(t, (int)idx);
    }
}

// ---------------- main gather kernel (index-sorted order) ----------------
__global__ void __launch_bounds__(NWARPS * 32)
cora_embed_kernel(const float* __restrict__ E,     // [VOCAB, 128]
                  const float* __restrict__ A,     // [8, 128]
                  const float* __restrict__ Bm,    // [VOCAB, 8]
                  const float* __restrict__ rp,    // [8]
                  float* __restrict__ out,         // [ntok, 128]
                  int ntok)
{
    __shared__ float e_buf[NWARPS][STAGES][DIM];
    __shared__ float b_buf[NWARPS][STAGES][RANK];

    const int lane = threadIdx.x & 31;
    const int w    = threadIdx.x >> 5;
    const int warp_global = blockIdx.x * NWARPS + w;

    uint64_t a2[RANK][2];
#pragma unroll
    for (int r = 0; r < RANK; r++) {
        float g = (rp[r] > RANK_THRESHOLD) ? SCALING : 0.0f;
        float4 av = reinterpret_cast<const float4*>(A)[r * (DIM / 4) + lane];
        a2[r][0] = pack2(av.x * g, av.y * g);
        a2[r][1] = pack2(av.z * g, av.w * g);
    }

    const int base = warp_global * CHUNK;
    if (base >= ntok) return;
    const int tend = min(base + CHUNK, ntok);
    const int nt = tend - base;

    const uint32_t e_base = (uint32_t)__cvta_generic_to_shared(&e_buf[w][0][0]);
    const uint32_t b_base = (uint32_t)__cvta_generic_to_shared(&b_buf[w][0][0]);

#pragma unroll
    for (int s = 0; s < STAGES; s++) {
        int t = base + s;
        if (t < tend) {
            uint32_t idx = (uint32_t)g_sorted[t].y;
            cp_async16(e_base + (uint32_t)(s * DIM + lane * 4) * 4,
                       E + (size_t)idx * DIM + lane * 4);
            if (lane < 2)
                cp_async16(b_base + (uint32_t)(s * RANK + lane * 4) * 4,
                           Bm + (size_t)idx * RANK + lane * 4);
        }
        cp_commit();
    }

    for (int i = 0; i < nt; i++) {
        asm volatile("cp.async.wait_group %0;\n" :: "n"(STAGES - 1));
        __syncwarp();

        const int s = i & (STAGES - 1);
        float4 e  = *reinterpret_cast<const float4*>(&e_buf[w][s][lane * 4]);
        float4 b0 = *reinterpret_cast<const float4*>(&b_buf[w][s][0]);
        float4 b1 = *reinterpret_cast<const float4*>(&b_buf[w][s][4]);

        __syncwarp();

        int t = base + i + STAGES;
        if (t < tend) {
            uint32_t idx = (uint32_t)g_sorted[t].y;
            cp_async16(e_base + (uint32_t)(s * DIM + lane * 4) * 4,
                       E + (size_t)idx * DIM + lane * 4);
            if (lane < 2)
                cp_async16(b_base + (uint32_t)(s * RANK + lane * 4) * 4,
                           Bm + (size_t)idx * RANK + lane * 4);
        }
        cp_commit();

        uint64_t o0 = pack2(e.x, e.y);
        uint64_t o1 = pack2(e.z, e.w);
        uint64_t bb;
        bb = bcast2(b0.x); o0 = fma2(bb, a2[0][0], o0); o1 = fma2(bb, a2[0][1], o1);
        bb = bcast2(b0.y); o0 = fma2(bb, a2[1][0], o0); o1 = fma2(bb, a2[1][1], o1);
        bb = bcast2(b0.z); o0 = fma2(bb, a2[2][0], o0); o1 = fma2(bb, a2[2][1], o1);
        bb = bcast2(b0.w); o0 = fma2(bb, a2[3][0], o0); o1 = fma2(bb, a2[3][1], o1);
        bb = bcast2(b1.x); o0 = fma2(bb, a2[4][0], o0); o1 = fma2(bb, a2[4][1], o1);
        bb = bcast2(b1.y); o0 = fma2(bb, a2[5][0], o0); o1 = fma2(bb, a2[5][1], o1);
        bb = bcast2(b1.z); o0 = fma2(bb, a2[6][0], o0); o1 = fma2(bb, a2[6][1], o1);
        bb = bcast2(b1.w); o0 = fma2(bb, a2[7][0], o0); o1 = fma2(bb, a2[7][1], o1);

        float4 o;
        unpack2(o0, o.x, o.y);
        unpack2(o1, o.z, o.w);

        int pos = g_sorted[base + i].x;
        __stcs(reinterpret_cast<float4*>(out + (size_t)pos * DIM) + lane, o);
    }
}

// ---------------- fallback (direct order) ----------------
__global__ void __launch_bounds__(NWARPS * 32)
cora_embed_direct(const void* __restrict__ xv,
                  const float* __restrict__ E, const float* __restrict__ A,
                  const float* __restrict__ Bm, const float* __restrict__ rp,
                  float* __restrict__ out, int ntok)
{
    __shared__ float e_buf[NWARPS][STAGES][DIM];
    __shared__ float b_buf[NWARPS][STAGES][RANK];
    const int lane = threadIdx.x & 31;
    const int w    = threadIdx.x >> 5;
    const int warp_global = blockIdx.x * NWARPS + w;
    const bool is64 = detect_is64(xv);
    const long long* x64 = reinterpret_cast<const long long*>(xv);
    const int*       x32 = reinterpret_cast<const int*>(xv);

    uint64_t a2[RANK][2];
#pragma unroll
    for (int r = 0; r < RANK; r++) {
        float g = (rp[r] > RANK_THRESHOLD) ? SCALING : 0.0f;
        float4 av = reinterpret_cast<const float4*>(A)[r * (DIM / 4) + lane];
        a2[r][0] = pack2(av.x * g, av.y * g);
        a2[r][1] = pack2(av.z * g, av.w * g);
    }
    const int base = warp_global * CHUNK;
    if (base >= ntok) return;
    const int tend = min(base + CHUNK, ntok);
    const int nt = tend - base;
    const uint32_t e_base = (uint32_t)__cvta_generic_to_shared(&e_buf[w][0][0]);
    const uint32_t b_base = (uint32_t)__cvta_generic_to_shared(&b_buf[w][0][0]);
#pragma unroll
    for (int s = 0; s < STAGES; s++) {
        int t = base + s;
        if (t < tend) {
            uint32_t idx = is64 ? (uint32_t)x64[t] : (uint32_t)x32[t];
            cp_async16(e_base + (uint32_t)(s * DIM + lane * 4) * 4,
                       E + (size_t)idx * DIM + lane * 4);
            if (lane < 2)
                cp_async16(b_base + (uint32_t)(s * RANK + lane * 4) * 4,
                           Bm + (size_t)idx * RANK + lane * 4);
        }
        cp_commit();
    }
    for (int i = 0; i < nt; i++) {
        asm volatile("cp.async.wait_group %0;\n" :: "n"(STAGES - 1));
        __syncwarp();
        const int s = i & (STAGES - 1);
        float4 e  = *reinterpret_cast<const float4*>(&e_buf[w][s][lane * 4]);
        float4 b0 = *reinterpret_cast<const float4*>(&b_buf[w][s][0]);
        float4 b1 = *reinterpret_cast<const float4*>(&b_buf[w][s][4]);
        __syncwarp();
        int t = base + i + STAGES;
        if (t < tend) {
            uint32_t idx = is64 ? (uint32_t)x64[t] : (uint32_t)x32[t];
            cp_async16(e_base + (uint32_t)(s * DIM + lane * 4) * 4,
                       E + (size_t)idx * DIM + lane * 4);
            if (lane < 2)
                cp_async16(b_base + (uint32_t)(s * RANK + lane * 4) * 4,
                           Bm + (size_t)idx * RANK + lane * 4);
        }
        cp_commit();
        uint64_t o0 = pack2(e.x, e.y);
        uint64_t o1 = pack2(e.z, e.w);
        uint64_t bb;
        bb = bcast2(b0.x); o0 = fma2(bb, a2[0][0], o0); o1 = fma2(bb, a2[0][1], o1);
        bb = bcast2(b0.y); o0 = fma2(bb, a2[1][0], o0); o1 = fma2(bb, a2[1][1], o1);
        bb = bcast2(b0.z); o0 = fma2(bb, a2[2][0], o0); o1 = fma2(bb, a2[2][1], o1);
        bb = bcast2(b0.w); o0 = fma2(bb, a2[3][0], o0); o1 = fma2(bb, a2[3][1], o1);
        bb = bcast2(b1.x); o0 = fma2(bb, a2[4][0], o0); o1 = fma2(bb, a2[4][1], o1);
        bb = bcast2(b1.y); o0 = fma2(bb, a2[5][0], o0); o1 = fma2(bb, a2[5][1], o1);
        bb = bcast2(b1.z); o0 = fma2(bb, a2[6][0], o0); o1 = fma2(bb, a2[6][1], o1);
        bb = bcast2(b1.w); o0 = fma2(bb, a2[7][0], o0); o1 = fma2(bb, a2[7][1], o1);
        float4 o;
        unpack2(o0, o.x, o.y);
        unpack2(o1, o.z, o.w);
        __stcs(reinterpret_cast<float4*>(out + (size_t)(base + i) * DIM) + lane, o);
    }
}

extern "C" void kernel_launch(void* const* d_in, const int* in_sizes, int n_in,
                              void* d_out, int out_size)
{
    const void*  x  = d_in[0];
    const float* E  = (const float*)d_in[1];
    const float* A  = (const float*)d_in[2];
    const float* Bm = (const float*)d_in[3];
    const float* rp = (const float*)d_in[4];
    float* out = (float*)d_out;

    const int ntok = out_size / DIM;
    const int tok_per_block = NWARPS * CHUNK;
    int blocks = (ntok + tok_per_block - 1) / tok_per_block;

    if (ntok <= MAXTOK && ntok >= 32) {
        hist_kernel<<<592, 256>>>(x, ntok);
        scan_kernel<<<1, NBUCK>>>();
        int sblocks = (ntok + SCHUNK - 1) / SCHUNK;
        scatter_kernel<<<sblocks, 512>>>(x, ntok);
        cora_embed_kernel<<<blocks, NWARPS * 32>>>(E, A, Bm, rp, out, ntok);
    } else {
        cora_embed_direct<<<blocks, NWARPS * 32>>>(x, E, A, Bm, rp, out, ntok);
    }
}

// round 12
// speedup vs baseline: 1.3799x; 1.0149x over previous
#include <cuda_runtime.h>
#include <cuda_bf16.h>
#include <cstdint>

#define VOCAB 500000
#define DIM 128
#define RANK 8
#define SCALING 2.0f
#define RANK_THRESHOLD 0.1f

#define NWARPS 8
#define STAGES 8
#define CHUNK 64

#define NBUCK 1024
#define BUCK_SHIFT 9          // bucket = idx >> 9
#define MAXTOK (1 << 20)
#define SCHUNK 2048           // tokens per scatter block

// ---- sort scratch (static device arrays; no allocation) ----
// Invariant at kernel_launch entry (and restored for every graph replay):
// g_hist == 0, g_done == 0.
__device__ int  g_hist[NBUCK];
__device__ int  g_offs[NBUCK];
__device__ int  g_done;
__device__ int2 g_sorted[MAXTOK];   // .x = original pos, .y = vocab idx

__device__ __forceinline__ void cp_async16(uint32_t smem_addr, const void* gptr) {
    asm volatile("cp.async.cg.shared.global [%0], [%1], 16;\n"
                 :: "r"(smem_addr), "l"(gptr));
}
__device__ __forceinline__ void cp_commit() {
    asm volatile("cp.async.commit_group;\n");
}

// ---- packed f32x2 helpers ----
__device__ __forceinline__ uint64_t pack2(float lo, float hi) {
    uint64_t r; asm("mov.b64 %0, {%1, %2};" : "=l"(r) : "f"(lo), "f"(hi)); return r;
}
__device__ __forceinline__ uint64_t bcast2(float v) {
    uint64_t r; asm("mov.b64 %0, {%1, %1};" : "=l"(r) : "f"(v)); return r;
}
__device__ __forceinline__ uint64_t fma2(uint64_t a, uint64_t b, uint64_t c) {
    uint64_t d; asm("fma.rn.f32x2 %0, %1, %2, %3;" : "=l"(d) : "l"(a), "l"(b), "l"(c)); return d;
}
__device__ __forceinline__ void unpack2(uint64_t v, float& lo, float& hi) {
    asm("mov.b64 {%0, %1}, %2;" : "=f"(lo), "=f"(hi) : "l"(v));
}

// warp-uniform index-dtype detection (first 32 int64 views)
__device__ __forceinline__ bool detect_is64(const void* xv) {
    const long long* x64 = reinterpret_cast<const long long*>(xv);
    long long probe = x64[threadIdx.x & 31];
    bool bad = (probe < 0) || (probe >= (long long)VOCAB);
    return (__ballot_sync(0xFFFFFFFFu, bad) == 0u);
}

// ---------------- fused histogram + scan (last-block pattern) ----------------
__global__ void __launch_bounds__(256)
hist_scan_kernel(const void* __restrict__ xv, int ntok) {
    __shared__ int sh[NBUCK];
    for (int i = threadIdx.x; i < NBUCK; i += blockDim.x) sh[i] = 0;
    __syncthreads();

    const bool is64 = detect_is64(xv);
    const long long* x64 = reinterpret_cast<const long long*>(xv);
    const int*       x32 = reinterpret_cast<const int*>(xv);
    for (int t = blockIdx.x * blockDim.x + threadIdx.x; t < ntok;
         t += gridDim.x * blockDim.x) {
        uint32_t idx = is64 ? (uint32_t)x64[t] : (uint32_t)x32[t];
        atomicAdd(&sh[idx >> BUCK_SHIFT], 1);
    }
    __syncthreads();
    for (int i = threadIdx.x; i < NBUCK; i += blockDim.x)
        if (sh[i]) atomicAdd(&g_hist[i], sh[i]);

    // ---- last finishing block performs the scan ----
    __shared__ int amLast;
    __threadfence();
    if (threadIdx.x == 0)
        amLast = (atomicAdd(&g_done, 1) == (int)gridDim.x - 1);
    __syncthreads();
    if (!amLast) return;

    // load full histogram, reset it for the next replay
    __shared__ int part[256];
    int local[4];
    const int b4 = threadIdx.x * 4;
    int s = 0;
#pragma unroll
    for (int k = 0; k < 4; k++) {
        local[k] = g_hist[b4 + k];
        g_hist[b4 + k] = 0;
        s += local[k];
    }
    part[threadIdx.x] = s;
    __syncthreads();
    for (int off = 1; off < 256; off <<= 1) {
        int add = (threadIdx.x >= off) ? part[threadIdx.x - off] : 0;
        __syncthreads();
        part[threadIdx.x] += add;
        __syncthreads();
    }
    int run = (threadIdx.x == 0) ? 0 : part[threadIdx.x - 1];
#pragma unroll
    for (int k = 0; k < 4; k++) {
        g_offs[b4 + k] = run;     // exclusive scan
        run += local[k];
    }
    if (threadIdx.x == 0) g_done = 0;   // restore invariant
}

// Block-aggregated scatter.
__global__ void __launch_bounds__(512)
scatter_kernel(const void* __restrict__ xv, int ntok) {
    __shared__ int s_cnt[NBUCK];
    __shared__ int s_base[NBUCK];

    const bool is64 = detect_is64(xv);
    const long long* x64 = reinterpret_cast<const long long*>(xv);
    const int*       x32 = reinterpret_cast<const int*>(xv);

    const int start = blockIdx.x * SCHUNK;
    const int end   = min(start + SCHUNK, ntok);

    for (int i = threadIdx.x; i < NBUCK; i += blockDim.x) s_cnt[i] = 0;
    __syncthreads();

    for (int t = start + threadIdx.x; t < end; t += blockDim.x) {
        uint32_t idx = is64 ? (uint32_t)x64[t] : (uint32_t)x32[t];
        atomicAdd(&s_cnt[idx >> BUCK_SHIFT], 1);
    }
    __syncthreads();

    for (int b = threadIdx.x; b < NBUCK; b += blockDim.x)
        s_base[b] = s_cnt[b] ? atomicAdd(&g_offs[b], s_cnt[b]) : 0;
    __syncthreads();

    for (int t = start + threadIdx.x; t < end; t += blockDim.x) {
        uint32_t idx = is64 ? (uint32_t)x64[t] : (uint32_t)x32[t];
        int p = atomicAdd(&s_base[idx >> BUCK_SHIFT], 1);
        g_sorted[p] = make_int2(t, (int)idx);
    }
}

// ---------------- main gather kernel (index-sorted order) ----------------
__global__ void __launch_bounds__(NWARPS * 32)
cora_embed_kernel(const float* __restrict__ E,
                  const float* __restrict__ A,
                  const float* __restrict__ Bm,
                  const float* __restrict__ rp,
                  float* __restrict__ out,
                  int ntok)
{
    __shared__ float e_buf[NWARPS][STAGES][DIM];
    __shared__ float b_buf[NWARPS][STAGES][RANK];

    const int lane = threadIdx.x & 31;
    const int w    = threadIdx.x >> 5;
    const int warp_global = blockIdx.x * NWARPS + w;

    uint64_t a2[RANK][2];
#pragma unroll
    for (int r = 0; r < RANK; r++) {
        float g = (rp[r] > RANK_THRESHOLD) ? SCALING : 0.0f;
        float4 av = reinterpret_cast<const float4*>(A)[r * (DIM / 4) + lane];
        a2[r][0] = pack2(av.x * g, av.y * g);
        a2[r][1] = pack2(av.z * g, av.w * g);
    }

    const int base = warp_global * CHUNK;
    if (base >= ntok) return;
    const int tend = min(base + CHUNK, ntok);
    const int nt = tend - base;

    const uint32_t e_base = (uint32_t)__cvta_generic_to_shared(&e_buf[w][0][0]);
    const uint32_t b_base = (uint32_t)__cvta_generic_to_shared(&b_buf[w][0][0]);

#pragma unroll
    for (int s = 0; s < STAGES; s++) {
        int t = base + s;
        if (t < tend) {
            uint32_t idx = (uint32_t)g_sorted[t].y;
            cp_async16(e_base + (uint32_t)(s * DIM + lane * 4) * 4,
                       E + (size_t)idx * DIM + lane * 4);
            if (lane < 2)
                cp_async16(b_base + (uint32_t)(s * RANK + lane * 4) * 4,
                           Bm + (size_t)idx * RANK + lane * 4);
        }
        cp_commit();
    }

    for (int i = 0; i < nt; i++) {
        asm volatile("cp.async.wait_group %0;\n" :: "n"(STAGES - 1));
        __syncwarp();

        const int s = i & (STAGES - 1);
        float4 e  = *reinterpret_cast<const float4*>(&e_buf[w][s][lane * 4]);
        float4 b0 = *reinterpret_cast<const float4*>(&b_buf[w][s][0]);
        float4 b1 = *reinterpret_cast<const float4*>(&b_buf[w][s][4]);

        __syncwarp();

        int t = base + i + STAGES;
        if (t < tend) {
            uint32_t idx = (uint32_t)g_sorted[t].y;
            cp_async16(e_base + (uint32_t)(s * DIM + lane * 4) * 4,
                       E + (size_t)idx * DIM + lane * 4);
            if (lane < 2)
                cp_async16(b_base + (uint32_t)(s * RANK + lane * 4) * 4,
                           Bm + (size_t)idx * RANK + lane * 4);
        }
        cp_commit();

        uint64_t o0 = pack2(e.x, e.y);
        uint64_t o1 = pack2(e.z, e.w);
        uint64_t bb;
        bb = bcast2(b0.x); o0 = fma2(bb, a2[0][0], o0); o1 = fma2(bb, a2[0][1], o1);
        bb = bcast2(b0.y); o0 = fma2(bb, a2[1][0], o0); o1 = fma2(bb, a2[1][1], o1);
        bb = bcast2(b0.z); o0 = fma2(bb, a2[2][0], o0); o1 = fma2(bb, a2[2][1], o1);
        bb = bcast2(b0.w); o0 = fma2(bb, a2[3][0], o0); o1 = fma2(bb, a2[3][1], o1);
        bb = bcast2(b1.x); o0 = fma2(bb, a2[4][0], o0); o1 = fma2(bb, a2[4][1], o1);
        bb = bcast2(b1.y); o0 = fma2(bb, a2[5][0], o0); o1 = fma2(bb, a2[5][1], o1);
        bb = bcast2(b1.z); o0 = fma2(bb, a2[6][0], o0); o1 = fma2(bb, a2[6][1], o1);
        bb = bcast2(b1.w); o0 = fma2(bb, a2[7][0], o0); o1 = fma2(bb, a2[7][1], o1);

        float4 o;
        unpack2(o0, o.x, o.y);
        unpack2(o1, o.z, o.w);

        int pos = g_sorted[base + i].x;
        __stcs(reinterpret_cast<float4*>(out + (size_t)pos * DIM) + lane, o);
    }
}

// ---------------- fallback (direct order) ----------------
__global__ void __launch_bounds__(NWARPS * 32)
cora_embed_direct(const void* __restrict__ xv,
                  const float* __restrict__ E, const float* __restrict__ A,
                  const float* __restrict__ Bm, const float* __restrict__ rp,
                  float* __restrict__ out, int ntok)
{
    __shared__ float e_buf[NWARPS][STAGES][DIM];
    __shared__ float b_buf[NWARPS][STAGES][RANK];
    const int lane = threadIdx.x & 31;
    const int w    = threadIdx.x >> 5;
    const int warp_global = blockIdx.x * NWARPS + w;
    const bool is64 = detect_is64(xv);
    const long long* x64 = reinterpret_cast<const long long*>(xv);
    const int*       x32 = reinterpret_cast<const int*>(xv);

    uint64_t a2[RANK][2];
#pragma unroll
    for (int r = 0; r < RANK; r++) {
        float g = (rp[r] > RANK_THRESHOLD) ? SCALING : 0.0f;
        float4 av = reinterpret_cast<const float4*>(A)[r * (DIM / 4) + lane];
        a2[r][0] = pack2(av.x * g, av.y * g);
        a2[r][1] = pack2(av.z * g, av.w * g);
    }
    const int base = warp_global * CHUNK;
    if (base >= ntok) return;
    const int tend = min(base + CHUNK, ntok);
    const int nt = tend - base;
    const uint32_t e_base = (uint32_t)__cvta_generic_to_shared(&e_buf[w][0][0]);
    const uint32_t b_base = (uint32_t)__cvta_generic_to_shared(&b_buf[w][0][0]);
#pragma unroll
    for (int s = 0; s < STAGES; s++) {
        int t = base + s;
        if (t < tend) {
            uint32_t idx = is64 ? (uint32_t)x64[t] : (uint32_t)x32[t];
            cp_async16(e_base + (uint32_t)(s * DIM + lane * 4) * 4,
                       E + (size_t)idx * DIM + lane * 4);
            if (lane < 2)
                cp_async16(b_base + (uint32_t)(s * RANK + lane * 4) * 4,
                           Bm + (size_t)idx * RANK + lane * 4);
        }
        cp_commit();
    }
    for (int i = 0; i < nt; i++) {
        asm volatile("cp.async.wait_group %0;\n" :: "n"(STAGES - 1));
        __syncwarp();
        const int s = i & (STAGES - 1);
        float4 e  = *reinterpret_cast<const float4*>(&e_buf[w][s][lane * 4]);
        float4 b0 = *reinterpret_cast<const float4*>(&b_buf[w][s][0]);
        float4 b1 = *reinterpret_cast<const float4*>(&b_buf[w][s][4]);
        __syncwarp();
        int t = base + i + STAGES;
        if (t < tend) {
            uint32_t idx = is64 ? (uint32_t)x64[t] : (uint32_t)x32[t];
            cp_async16(e_base + (uint32_t)(s * DIM + lane * 4) * 4,
                       E + (size_t)idx * DIM + lane * 4);
            if (lane < 2)
                cp_async16(b_base + (uint32_t)(s * RANK + lane * 4) * 4,
                           Bm + (size_t)idx * RANK + lane * 4);
        }
        cp_commit();
        uint64_t o0 = pack2(e.x, e.y);
        uint64_t o1 = pack2(e.z, e.w);
        uint64_t bb;
        bb = bcast2(b0.x); o0 = fma2(bb, a2[0][0], o0); o1 = fma2(bb, a2[0][1], o1);
        bb = bcast2(b0.y); o0 = fma2(bb, a2[1][0], o0); o1 = fma2(bb, a2[1][1], o1);
        bb = bcast2(b0.z); o0 = fma2(bb, a2[2][0], o0); o1 = fma2(bb, a2[2][1], o1);
        bb = bcast2(b0.w); o0 = fma2(bb, a2[3][0], o0); o1 = fma2(bb, a2[3][1], o1);
        bb = bcast2(b1.x); o0 = fma2(bb, a2[4][0], o0); o1 = fma2(bb, a2[4][1], o1);
        bb = bcast2(b1.y); o0 = fma2(bb, a2[5][0], o0); o1 = fma2(bb, a2[5][1], o1);
        bb = bcast2(b1.z); o0 = fma2(bb, a2[6][0], o0); o1 = fma2(bb, a2[6][1], o1);
        bb = bcast2(b1.w); o0 = fma2(bb, a2[7][0], o0); o1 = fma2(bb, a2[7][1], o1);
        float4 o;
        unpack2(o0, o.x, o.y);
        unpack2(o1, o.z, o.w);
        __stcs(reinterpret_cast<float4*>(out + (size_t)(base + i) * DIM) + lane, o);
    }
}

extern "C" void kernel_launch(void* const* d_in, const int* in_sizes, int n_in,
                              void* d_out, int out_size)
{
    const void*  x  = d_in[0];
    const float* E  = (const float*)d_in[1];
    const float* A  = (const float*)d_in[2];
    const float* Bm = (const float*)d_in[3];
    const float* rp = (const float*)d_in[4];
    float* out = (float*)d_out;

    const int ntok = out_size / DIM;
    const int tok_per_block = NWARPS * CHUNK;
    int blocks = (ntok + tok_per_block - 1) / tok_per_block;

    if (ntok <= MAXTOK && ntok >= 32) {
        hist_scan_kernel<<<592, 256>>>(x, ntok);
        int sblocks = (ntok + SCHUNK - 1) / SCHUNK;
        scatter_kernel<<<sblocks, 512>>>(x, ntok);
        cora_embed_kernel<<<blocks, NWARPS * 32>>>(E, A, Bm, rp, out, ntok);
    } else {
        cora_embed_direct<<<blocks, NWARPS * 32>>>(x, E, A, Bm, rp, out, ntok);
    }
}